// round 1
// baseline (speedup 1.0000x reference)
#include <cuda_runtime.h>
#include <cuda_bf16.h>
#include <math.h>

// Problem dims (fixed by the dataset)
#define BB   2
#define SS   2048
#define DD   1024
#define HH   16
#define KVH  8
#define DK   64
#define FD   2752
#define NL   4
#define VV   32000
#define MM   (BB*SS)          // 4096 token rows

// ---------------- scratch (device globals: no allocations allowed) ----------
__device__ float g_x [MM*DD];
__device__ float g_h [MM*DD];
__device__ float g_q [MM*DD];
__device__ float g_k [MM*(KVH*DK)];
__device__ float g_v [MM*(KVH*DK)];
__device__ float g_o [MM*DD];
__device__ float g_f1[(size_t)MM*FD];
__device__ float g_f2[(size_t)MM*FD];

// ---------------- embedding gather ----------------
__global__ void embed_kernel(const int* __restrict__ tokens,
                             const float* __restrict__ emb,
                             float* __restrict__ x) {
    int row = blockIdx.x;                      // 0..MM-1
    int tok = tokens[row];
    const float4* src = (const float4*)(emb + (size_t)tok * DD);
    float4*       dst = (float4*)(x + (size_t)row * DD);
    dst[threadIdx.x] = src[threadIdx.x];       // 256 threads * float4 = 1024
}

// ---------------- rmsnorm ----------------
__global__ void rmsnorm_kernel(const float* __restrict__ x,
                               const float* __restrict__ g,
                               float* __restrict__ out) {
    int row = blockIdx.x;
    const float4* xr = (const float4*)(x + (size_t)row * DD);
    float4 v = xr[threadIdx.x];
    float ss = v.x*v.x + v.y*v.y + v.z*v.z + v.w*v.w;
    #pragma unroll
    for (int o = 16; o; o >>= 1) ss += __shfl_xor_sync(0xffffffffu, ss, o);
    __shared__ float red[8];
    if ((threadIdx.x & 31) == 0) red[threadIdx.x >> 5] = ss;
    __syncthreads();
    if (threadIdx.x < 8) {
        float r = red[threadIdx.x];
        #pragma unroll
        for (int o = 4; o; o >>= 1) r += __shfl_xor_sync(0xffu, r, o);
        if (threadIdx.x == 0) red[0] = r;
    }
    __syncthreads();
    float inv = rsqrtf(red[0] * (1.0f / DD) + 1e-6f);
    const float4* g4 = (const float4*)g;
    float4 gg = g4[threadIdx.x];
    float4 ov = make_float4(v.x*inv*gg.x, v.y*inv*gg.y, v.z*inv*gg.z, v.w*inv*gg.w);
    ((float4*)(out + (size_t)row * DD))[threadIdx.x] = ov;
}

// ---------------- rope (interleaved pairs) ----------------
__global__ void rope_kernel(float* __restrict__ buf,
                            const float* __restrict__ cosb,
                            const float* __restrict__ sinb,
                            int nheads, int total) {
    int idx = blockIdx.x * blockDim.x + threadIdx.x;
    if (idx >= total) return;
    int p    = idx & 31;               // pair index 0..31
    int hrow = idx >> 5;               // (row, head)
    int row  = hrow / nheads;
    int s    = row & (SS - 1);
    float c  = cosb[s * 32 + p];
    float sn = sinb[s * 32 + p];
    float* base = buf + (size_t)hrow * DK + p * 2;
    float xr = base[0], xi = base[1];
    base[0] = xr * c - xi * sn;
    base[1] = xr * sn + xi * c;
}

// ---------------- flash attention (online softmax, causal, GQA n_rep=2) ----
// block: (32,16) -> one warp per query row, 16 query rows per block
#define ABM 16
#define ABN 32
__global__ __launch_bounds__(512)
void attn_kernel(const float* __restrict__ Q, const float* __restrict__ K,
                 const float* __restrict__ V, float* __restrict__ O) {
    int q0   = blockIdx.x * ABM;
    int h    = blockIdx.y;
    int b    = blockIdx.z;
    int kh   = h >> 1;                 // n_rep = 2
    int lane = threadIdx.x;
    int wy   = threadIdx.y;
    int t    = wy * 32 + lane;

    __shared__ float q_sh[ABM][DK];
    __shared__ float k_sh[ABN][DK + 1];
    __shared__ float v_sh[ABN][DK + 1];

    for (int idx = t; idx < ABM * DK; idx += 512) {
        int r = idx >> 6, c = idx & 63;
        q_sh[r][c] = Q[((size_t)(b * SS + q0 + r) * HH + h) * DK + c] * 0.125f;
    }
    __syncthreads();

    int   iglob = q0 + wy;
    float m = -1e30f, l = 0.f, acc0 = 0.f, acc1 = 0.f;
    int ntiles = (q0 + ABM - 1) / ABN + 1;     // keys fully cover causal span

    for (int kt = 0; kt < ntiles; kt++) {
        int kbase = kt * ABN;
        for (int idx = t; idx < ABN * DK; idx += 512) {
            int r = idx >> 6, c = idx & 63;
            size_t off = ((size_t)(b * SS + kbase + r) * KVH + kh) * DK + c;
            k_sh[r][c] = K[off];
            v_sh[r][c] = V[off];
        }
        __syncthreads();

        float s = 0.f;
        #pragma unroll 16
        for (int d = 0; d < DK; d++) s += q_sh[wy][d] * k_sh[lane][d];
        if (kbase + lane > iglob) s = -1e30f;

        float mt = s;
        #pragma unroll
        for (int o = 16; o; o >>= 1) mt = fmaxf(mt, __shfl_xor_sync(0xffffffffu, mt, o));
        float mnew = fmaxf(m, mt);
        float corr = __expf(m - mnew);
        float p    = __expf(s - mnew);
        float ps   = p;
        #pragma unroll
        for (int o = 16; o; o >>= 1) ps += __shfl_xor_sync(0xffffffffu, ps, o);
        l = l * corr + ps;
        acc0 *= corr; acc1 *= corr;
        m = mnew;
        #pragma unroll
        for (int jj = 0; jj < 32; jj++) {
            float pj = __shfl_sync(0xffffffffu, p, jj);
            acc0 += pj * v_sh[jj][lane];
            acc1 += pj * v_sh[jj][lane + 32];
        }
        __syncthreads();
    }
    float invl = 1.f / l;
    size_t ob = ((size_t)(b * SS + iglob) * HH + h) * DK;
    O[ob + lane]      = acc0 * invl;
    O[ob + lane + 32] = acc1 * invl;
}

// ---------------- SGEMM NN: C = A[M,K] @ B[K,N] (+bias)(+residual) --------
#define GBM 128
#define GBN 128
#define GBK 8
__global__ __launch_bounds__(256)
void gemm_nn_kernel(const float* __restrict__ A, const float* __restrict__ Bm,
                    const float* __restrict__ bias, const float* __restrict__ res,
                    float* __restrict__ C, int Md, int Nd, int Kd) {
    __shared__ float As[GBK][GBM];
    __shared__ float Bs[GBK][GBN];
    int t  = threadIdx.x;
    int bm = blockIdx.y * GBM;
    int bn = blockIdx.x * GBN;
    int tr = t >> 4, tc = t & 15;
    int aRow = t >> 1, aCol = (t & 1) * 4;
    int bRow = t >> 5, bCol = (t & 31) * 4;
    float acc[8][8] = {};

    for (int k0 = 0; k0 < Kd; k0 += GBK) {
        float4 av = *(const float4*)(A + (size_t)(bm + aRow) * Kd + k0 + aCol);
        As[aCol + 0][aRow] = av.x; As[aCol + 1][aRow] = av.y;
        As[aCol + 2][aRow] = av.z; As[aCol + 3][aRow] = av.w;
        float4 bv = make_float4(0.f, 0.f, 0.f, 0.f);
        if (bn + bCol < Nd)
            bv = *(const float4*)(Bm + (size_t)(k0 + bRow) * Nd + bn + bCol);
        *(float4*)&Bs[bRow][bCol] = bv;
        __syncthreads();
        #pragma unroll
        for (int kk = 0; kk < GBK; kk++) {
            float a[8], b[8];
            *(float4*)&a[0] = *(const float4*)&As[kk][tr * 8];
            *(float4*)&a[4] = *(const float4*)&As[kk][tr * 8 + 4];
            *(float4*)&b[0] = *(const float4*)&Bs[kk][tc * 8];
            *(float4*)&b[4] = *(const float4*)&Bs[kk][tc * 8 + 4];
            #pragma unroll
            for (int i = 0; i < 8; i++)
                #pragma unroll
                for (int j = 0; j < 8; j++)
                    acc[i][j] += a[i] * b[j];
        }
        __syncthreads();
    }
    #pragma unroll
    for (int i = 0; i < 8; i++) {
        int mrow = bm + tr * 8 + i;
        #pragma unroll
        for (int j = 0; j < 8; j += 4) {
            int n = bn + tc * 8 + j;
            if (n < Nd) {
                float4 cv = make_float4(acc[i][j], acc[i][j+1], acc[i][j+2], acc[i][j+3]);
                if (bias) {
                    float4 bb = *(const float4*)(bias + n);
                    cv.x += bb.x; cv.y += bb.y; cv.z += bb.z; cv.w += bb.w;
                }
                if (res) {
                    float4 rr = *(const float4*)(res + (size_t)mrow * Nd + n);
                    cv.x += rr.x; cv.y += rr.y; cv.z += rr.z; cv.w += rr.w;
                }
                *(float4*)(C + (size_t)mrow * Nd + n) = cv;
            }
        }
    }
}

// ---------------- SGEMM NT: C = A[M,K] @ E[N,K]^T (LM head) ----------------
__global__ __launch_bounds__(256)
void gemm_nt_kernel(const float* __restrict__ A, const float* __restrict__ E,
                    float* __restrict__ C, int Md, int Nd, int Kd) {
    __shared__ float As[GBK][GBM];
    __shared__ float Bs[GBK][GBN];
    int t  = threadIdx.x;
    int bm = blockIdx.y * GBM;
    int bn = blockIdx.x * GBN;
    int tr = t >> 4, tc = t & 15;
    int aRow = t >> 1, aCol = (t & 1) * 4;
    float acc[8][8] = {};

    for (int k0 = 0; k0 < Kd; k0 += GBK) {
        float4 av = *(const float4*)(A + (size_t)(bm + aRow) * Kd + k0 + aCol);
        As[aCol + 0][aRow] = av.x; As[aCol + 1][aRow] = av.y;
        As[aCol + 2][aRow] = av.z; As[aCol + 3][aRow] = av.w;
        float4 ev = *(const float4*)(E + (size_t)(bn + aRow) * Kd + k0 + aCol);
        Bs[aCol + 0][aRow] = ev.x; Bs[aCol + 1][aRow] = ev.y;
        Bs[aCol + 2][aRow] = ev.z; Bs[aCol + 3][aRow] = ev.w;
        __syncthreads();
        #pragma unroll
        for (int kk = 0; kk < GBK; kk++) {
            float a[8], b[8];
            *(float4*)&a[0] = *(const float4*)&As[kk][tr * 8];
            *(float4*)&a[4] = *(const float4*)&As[kk][tr * 8 + 4];
            *(float4*)&b[0] = *(const float4*)&Bs[kk][tc * 8];
            *(float4*)&b[4] = *(const float4*)&Bs[kk][tc * 8 + 4];
            #pragma unroll
            for (int i = 0; i < 8; i++)
                #pragma unroll
                for (int j = 0; j < 8; j++)
                    acc[i][j] += a[i] * b[j];
        }
        __syncthreads();
    }
    #pragma unroll
    for (int i = 0; i < 8; i++) {
        int mrow = bm + tr * 8 + i;
        #pragma unroll
        for (int j = 0; j < 8; j += 4) {
            int n = bn + tc * 8 + j;
            float4 cv = make_float4(acc[i][j], acc[i][j+1], acc[i][j+2], acc[i][j+3]);
            *(float4*)(C + (size_t)mrow * Nd + n) = cv;
        }
    }
}

// ---------------- silu(f1)*f2 -> f1 ----------------
__global__ void silumul_kernel(float* __restrict__ f1, const float* __restrict__ f2, int n) {
    int i = blockIdx.x * blockDim.x + threadIdx.x;
    if (i < n) {
        float a = f1[i];
        float s = a / (1.0f + __expf(-a));
        f1[i] = s * f2[i];
    }
}

// ---------------- host driver ----------------
extern "C" void kernel_launch(void* const* d_in, const int* in_sizes, int n_in,
                              void* d_out, int out_size) {
    const int*   tokens = (const int*)  d_in[0];
    const float* emb    = (const float*)d_in[1];
    const float* wq = (const float*)d_in[2];
    const float* bq = (const float*)d_in[3];
    const float* wk = (const float*)d_in[4];
    const float* bk = (const float*)d_in[5];
    const float* wv = (const float*)d_in[6];
    const float* bv = (const float*)d_in[7];
    const float* wo = (const float*)d_in[8];
    const float* bo = (const float*)d_in[9];
    const float* w1 = (const float*)d_in[10];
    const float* b1 = (const float*)d_in[11];
    const float* w2 = (const float*)d_in[12];
    const float* b2 = (const float*)d_in[13];
    const float* w3 = (const float*)d_in[14];
    const float* b3 = (const float*)d_in[15];
    const float* g1 = (const float*)d_in[16];
    const float* g2 = (const float*)d_in[17];
    const float* gpost = (const float*)d_in[18];
    const float* fcos  = (const float*)d_in[19];
    const float* fsin  = (const float*)d_in[20];
    float* out = (float*)d_out;

    float *x, *h, *q, *k, *v, *o, *f1, *f2;
    cudaGetSymbolAddress((void**)&x,  g_x);
    cudaGetSymbolAddress((void**)&h,  g_h);
    cudaGetSymbolAddress((void**)&q,  g_q);
    cudaGetSymbolAddress((void**)&k,  g_k);
    cudaGetSymbolAddress((void**)&v,  g_v);
    cudaGetSymbolAddress((void**)&o,  g_o);
    cudaGetSymbolAddress((void**)&f1, g_f1);
    cudaGetSymbolAddress((void**)&f2, g_f2);

    embed_kernel<<<MM, 256>>>(tokens, emb, x);

    const int KVN = KVH * DK;   // 512
    for (int l = 0; l < NL; l++) {
        rmsnorm_kernel<<<MM, 256>>>(x, g1 + (size_t)l * DD, h);

        gemm_nn_kernel<<<dim3(DD / GBN, MM / GBM), 256>>>(
            h, wq + (size_t)l * DD * DD, bq + (size_t)l * DD, nullptr, q, MM, DD, DD);
        gemm_nn_kernel<<<dim3(KVN / GBN, MM / GBM), 256>>>(
            h, wk + (size_t)l * DD * KVN, bk + (size_t)l * KVN, nullptr, k, MM, KVN, DD);
        gemm_nn_kernel<<<dim3(KVN / GBN, MM / GBM), 256>>>(
            h, wv + (size_t)l * DD * KVN, bv + (size_t)l * KVN, nullptr, v, MM, KVN, DD);

        int tq = MM * HH * 32,  tk = MM * KVH * 32;
        rope_kernel<<<(tq + 255) / 256, 256>>>(q, fcos, fsin, HH, tq);
        rope_kernel<<<(tk + 255) / 256, 256>>>(k, fcos, fsin, KVH, tk);

        attn_kernel<<<dim3(SS / ABM, HH, BB), dim3(32, 16)>>>(q, k, v, o);

        gemm_nn_kernel<<<dim3(DD / GBN, MM / GBM), 256>>>(
            o, wo + (size_t)l * DD * DD, bo + (size_t)l * DD, x, x, MM, DD, DD);

        rmsnorm_kernel<<<MM, 256>>>(x, g2 + (size_t)l * DD, h);

        int gnx = (FD + GBN - 1) / GBN;   // 22
        gemm_nn_kernel<<<dim3(gnx, MM / GBM), 256>>>(
            h, w1 + (size_t)l * DD * FD, b1 + (size_t)l * FD, nullptr, f1, MM, FD, DD);
        gemm_nn_kernel<<<dim3(gnx, MM / GBM), 256>>>(
            h, w2 + (size_t)l * DD * FD, b2 + (size_t)l * FD, nullptr, f2, MM, FD, DD);

        int nsm = MM * FD;
        silumul_kernel<<<(nsm + 255) / 256, 256>>>(f1, f2, nsm);

        gemm_nn_kernel<<<dim3(DD / GBN, MM / GBM), 256>>>(
            f1, w3 + (size_t)l * FD * DD, b3 + (size_t)l * DD, x, x, MM, DD, FD);
    }

    rmsnorm_kernel<<<MM, 256>>>(x, gpost, h);
    gemm_nt_kernel<<<dim3(VV / GBN, MM / GBM), 256>>>(h, emb, out, MM, VV, DD);
}

// round 3
// speedup vs baseline: 1.4721x; 1.4721x over previous
#include <cuda_runtime.h>
#include <cuda_bf16.h>
#include <math.h>

// Problem dims (fixed by the dataset)
#define BB   2
#define SS   2048
#define DD   1024
#define HH   16
#define KVH  8
#define DK   64
#define FD   2752
#define NL   4
#define VV   32000
#define MM   (BB*SS)          // 4096 token rows

// ---------------- scratch (device globals: no allocations allowed) ----------
__device__ float g_x [MM*DD];
__device__ float g_h [MM*DD];
__device__ float g_q [MM*DD];
__device__ float g_k [MM*(KVH*DK)];
__device__ float g_v [MM*(KVH*DK)];
__device__ float g_o [MM*DD];
__device__ float g_f1[(size_t)MM*FD];
__device__ float g_f2[(size_t)MM*FD];

// ---------------- embedding gather ----------------
__global__ void embed_kernel(const int* __restrict__ tokens,
                             const float* __restrict__ emb,
                             float* __restrict__ x) {
    int row = blockIdx.x;
    int tok = tokens[row];
    const float4* src = (const float4*)(emb + (size_t)tok * DD);
    float4*       dst = (float4*)(x + (size_t)row * DD);
    dst[threadIdx.x] = src[threadIdx.x];
}

// ---------------- rmsnorm ----------------
__global__ void rmsnorm_kernel(const float* __restrict__ x,
                               const float* __restrict__ g,
                               float* __restrict__ out) {
    int row = blockIdx.x;
    const float4* xr = (const float4*)(x + (size_t)row * DD);
    float4 v = xr[threadIdx.x];
    float ss = v.x*v.x + v.y*v.y + v.z*v.z + v.w*v.w;
    #pragma unroll
    for (int o = 16; o; o >>= 1) ss += __shfl_xor_sync(0xffffffffu, ss, o);
    __shared__ float red[8];
    if ((threadIdx.x & 31) == 0) red[threadIdx.x >> 5] = ss;
    __syncthreads();
    if (threadIdx.x < 8) {
        float r = red[threadIdx.x];
        #pragma unroll
        for (int o = 4; o; o >>= 1) r += __shfl_xor_sync(0xffu, r, o);
        if (threadIdx.x == 0) red[0] = r;
    }
    __syncthreads();
    float inv = rsqrtf(red[0] * (1.0f / DD) + 1e-6f);
    const float4* g4 = (const float4*)g;
    float4 gg = g4[threadIdx.x];
    float4 ov = make_float4(v.x*inv*gg.x, v.y*inv*gg.y, v.z*inv*gg.z, v.w*inv*gg.w);
    ((float4*)(out + (size_t)row * DD))[threadIdx.x] = ov;
}

// ---------------- rope (interleaved pairs) ----------------
__global__ void rope_kernel(float* __restrict__ buf,
                            const float* __restrict__ cosb,
                            const float* __restrict__ sinb,
                            int nheads, int total) {
    int idx = blockIdx.x * blockDim.x + threadIdx.x;
    if (idx >= total) return;
    int p    = idx & 31;
    int hrow = idx >> 5;
    int row  = hrow / nheads;
    int s    = row & (SS - 1);
    float c  = cosb[s * 32 + p];
    float sn = sinb[s * 32 + p];
    float* base = buf + (size_t)hrow * DK + p * 2;
    float xr = base[0], xi = base[1];
    base[0] = xr * c - xi * sn;
    base[1] = xr * sn + xi * c;
}

// ---------------- flash attention (online softmax, causal, GQA n_rep=2) ----
#define ABM 16
#define ABN 32
__global__ __launch_bounds__(512)
void attn_kernel(const float* __restrict__ Q, const float* __restrict__ K,
                 const float* __restrict__ V, float* __restrict__ O) {
    int q0   = blockIdx.x * ABM;
    int h    = blockIdx.y;
    int b    = blockIdx.z;
    int kh   = h >> 1;
    int lane = threadIdx.x;
    int wy   = threadIdx.y;
    int t    = wy * 32 + lane;

    __shared__ float q_sh[ABM][DK];
    __shared__ float k_sh[ABN][DK + 1];
    __shared__ float v_sh[ABN][DK + 1];

    for (int idx = t; idx < ABM * DK; idx += 512) {
        int r = idx >> 6, c = idx & 63;
        q_sh[r][c] = Q[((size_t)(b * SS + q0 + r) * HH + h) * DK + c] * 0.125f;
    }
    __syncthreads();

    int   iglob = q0 + wy;
    float m = -1e30f, l = 0.f, acc0 = 0.f, acc1 = 0.f;
    int ntiles = (q0 + ABM - 1) / ABN + 1;

    for (int kt = 0; kt < ntiles; kt++) {
        int kbase = kt * ABN;
        for (int idx = t; idx < ABN * DK; idx += 512) {
            int r = idx >> 6, c = idx & 63;
            size_t off = ((size_t)(b * SS + kbase + r) * KVH + kh) * DK + c;
            k_sh[r][c] = K[off];
            v_sh[r][c] = V[off];
        }
        __syncthreads();

        float s = 0.f;
        #pragma unroll 16
        for (int d = 0; d < DK; d++) s += q_sh[wy][d] * k_sh[lane][d];
        if (kbase + lane > iglob) s = -1e30f;

        float mt = s;
        #pragma unroll
        for (int o = 16; o; o >>= 1) mt = fmaxf(mt, __shfl_xor_sync(0xffffffffu, mt, o));
        float mnew = fmaxf(m, mt);
        float corr = __expf(m - mnew);
        float p    = __expf(s - mnew);
        float ps   = p;
        #pragma unroll
        for (int o = 16; o; o >>= 1) ps += __shfl_xor_sync(0xffffffffu, ps, o);
        l = l * corr + ps;
        acc0 *= corr; acc1 *= corr;
        m = mnew;
        #pragma unroll
        for (int jj = 0; jj < 32; jj++) {
            float pj = __shfl_sync(0xffffffffu, p, jj);
            acc0 += pj * v_sh[jj][lane];
            acc1 += pj * v_sh[jj][lane + 32];
        }
        __syncthreads();
    }
    float invl = 1.f / l;
    size_t ob = ((size_t)(b * SS + iglob) * HH + h) * DK;
    O[ob + lane]      = acc0 * invl;
    O[ob + lane + 32] = acc1 * invl;
}

// ================= 3xBF16 split tensor-core GEMM ===========================
// C[M,N] = A[M,K] @ op(B) (+bias)(+residual), fp32 in/out.
// Each operand split hi/lo in bf16; products hi*hi + lo*hi + hi*lo (fp32 acc).
//   NT=false : B is [K,N] row-major
//   NT=true  : B is [N,K] row-major (use B^T)  -> LM head
// Tiles: 128x128x16, 8 warps (2x4), warp tile 64x32, mma m16n8k16 bf16.
#define BM 128
#define BN 128
#define BKT 16
#define ASTR 12     // 8 kpairs + 4 pad (uint32)  -> frag reads conflict-free
#define BSTR 136    // 128 cols + 8 pad           -> frag reads conflict-free

__device__ __forceinline__ void split2(float x0, float x1,
                                       unsigned &hi, unsigned &lo) {
    __nv_bfloat162 h = __floats2bfloat162_rn(x0, x1);
    float h0 = __bfloat162float(h.x);
    float h1 = __bfloat162float(h.y);
    __nv_bfloat162 l = __floats2bfloat162_rn(x0 - h0, x1 - h1);
    hi = *reinterpret_cast<unsigned*>(&h);
    lo = *reinterpret_cast<unsigned*>(&l);
}

#define BF16MMA(D, Ar, Br)                                                    \
    asm volatile(                                                             \
        "mma.sync.aligned.m16n8k16.row.col.f32.bf16.bf16.f32 "                \
        "{%0,%1,%2,%3}, {%4,%5,%6,%7}, {%8,%9}, {%0,%1,%2,%3};"               \
        : "+f"(D[0]), "+f"(D[1]), "+f"(D[2]), "+f"(D[3])                      \
        : "r"(Ar[0]), "r"(Ar[1]), "r"(Ar[2]), "r"(Ar[3]),                     \
          "r"(Br[0]), "r"(Br[1]))

template<bool NT>
__global__ __launch_bounds__(256)
void gemm_tc_kernel(const float* __restrict__ A, const float* __restrict__ B,
                    const float* __restrict__ bias, const float* __restrict__ res,
                    float* __restrict__ C, int Nd, int Kd) {
    __shared__ unsigned AsH[2][BM][ASTR];
    __shared__ unsigned AsL[2][BM][ASTR];
    __shared__ unsigned BsH[2][8][BSTR];
    __shared__ unsigned BsL[2][8][BSTR];

    const int t    = threadIdx.x;
    const int lane = t & 31;
    const int warp = t >> 5;
    const int wm   = warp >> 2;          // 0..1
    const int wn   = warp & 3;           // 0..3
    const int bm   = blockIdx.y * BM;
    const int bn   = blockIdx.x * BN;

    // A staging: thread loads 2 float4 (rows arow, arow+64), 2 kpairs each
    const int arow  = t >> 2;            // 0..63
    const int acol4 = (t & 3) * 4;       // k offset 0,4,8,12
    const int akp   = (t & 3) * 2;       // kpair base

    // B staging: thread owns one column, 4 kpairs (half of the 8)
    const int bcol  = t & 127;
    const int bhalf = t >> 7;            // 0 or 1
    const bool bok  = NT || (bn + bcol < Nd);

    float acc[4][4][4] = {};
    float4 aR0, aR1;
    float  bReg[8];

    const int nkt = Kd / BKT;

    // ---- global load of tile kt into registers
    auto g_load = [&](int kt) {
        const int k0 = kt * BKT;
        aR0 = *(const float4*)(A + (size_t)(bm + arow)      * Kd + k0 + acol4);
        aR1 = *(const float4*)(A + (size_t)(bm + arow + 64) * Kd + k0 + acol4);
        if (NT) {
            const float* ep = B + (size_t)(bn + bcol) * Kd + k0 + bhalf * 8;
            float4 e0 = *(const float4*)(ep);
            float4 e1 = *(const float4*)(ep + 4);
            bReg[0] = e0.x; bReg[1] = e0.y; bReg[2] = e0.z; bReg[3] = e0.w;
            bReg[4] = e1.x; bReg[5] = e1.y; bReg[6] = e1.z; bReg[7] = e1.w;
        } else {
            #pragma unroll
            for (int j = 0; j < 4; j++) {
                int kk = k0 + (bhalf * 4 + j) * 2;
                if (bok) {
                    bReg[2*j]   = B[(size_t)kk       * Nd + bn + bcol];
                    bReg[2*j+1] = B[(size_t)(kk + 1) * Nd + bn + bcol];
                } else {
                    bReg[2*j] = 0.f; bReg[2*j+1] = 0.f;
                }
            }
        }
    };
    // ---- split + store registers into smem buffer buf
    auto s_store = [&](int buf) {
        split2(aR0.x, aR0.y, AsH[buf][arow][akp],        AsL[buf][arow][akp]);
        split2(aR0.z, aR0.w, AsH[buf][arow][akp + 1],    AsL[buf][arow][akp + 1]);
        split2(aR1.x, aR1.y, AsH[buf][arow+64][akp],     AsL[buf][arow+64][akp]);
        split2(aR1.z, aR1.w, AsH[buf][arow+64][akp + 1], AsL[buf][arow+64][akp + 1]);
        #pragma unroll
        for (int j = 0; j < 4; j++) {
            int kp = bhalf * 4 + j;
            split2(bReg[2*j], bReg[2*j+1], BsH[buf][kp][bcol], BsL[buf][kp][bcol]);
        }
    };

    g_load(0);
    s_store(0);
    __syncthreads();

    const int m0 = wm * 64;
    const int n0 = wn * 32;
    const int lq = lane >> 2;   // 0..7
    const int lr = lane & 3;    // 0..3

    for (int kt = 0; kt < nkt; kt++) {
        const int cur = kt & 1;
        if (kt + 1 < nkt) g_load(kt + 1);

        unsigned aH[4][4], aL[4][4], bH[4][2], bL[4][2];
        #pragma unroll
        for (int mi = 0; mi < 4; mi++) {
            int r = m0 + mi * 16 + lq;
            aH[mi][0] = AsH[cur][r    ][lr];     aH[mi][1] = AsH[cur][r + 8][lr];
            aH[mi][2] = AsH[cur][r    ][lr + 4]; aH[mi][3] = AsH[cur][r + 8][lr + 4];
            aL[mi][0] = AsL[cur][r    ][lr];     aL[mi][1] = AsL[cur][r + 8][lr];
            aL[mi][2] = AsL[cur][r    ][lr + 4]; aL[mi][3] = AsL[cur][r + 8][lr + 4];
        }
        #pragma unroll
        for (int ni = 0; ni < 4; ni++) {
            int c = n0 + ni * 8 + lq;
            bH[ni][0] = BsH[cur][lr][c]; bH[ni][1] = BsH[cur][lr + 4][c];
            bL[ni][0] = BsL[cur][lr][c]; bL[ni][1] = BsL[cur][lr + 4][c];
        }
        #pragma unroll
        for (int mi = 0; mi < 4; mi++)
            #pragma unroll
            for (int ni = 0; ni < 4; ni++) {
                BF16MMA(acc[mi][ni], aH[mi], bH[ni]);
                BF16MMA(acc[mi][ni], aL[mi], bH[ni]);
                BF16MMA(acc[mi][ni], aH[mi], bL[ni]);
            }

        if (kt + 1 < nkt) s_store((kt + 1) & 1);
        __syncthreads();
    }

    // ---- epilogue
    #pragma unroll
    for (int mi = 0; mi < 4; mi++) {
        int row = bm + m0 + mi * 16 + lq;
        #pragma unroll
        for (int ni = 0; ni < 4; ni++) {
            int col = bn + n0 + ni * 8 + lr * 2;
            if (col < Nd) {
                float v0 = acc[mi][ni][0], v1 = acc[mi][ni][1];
                float v2 = acc[mi][ni][2], v3 = acc[mi][ni][3];
                if (bias) {
                    float bx = bias[col], by = bias[col + 1];
                    v0 += bx; v1 += by; v2 += bx; v3 += by;
                }
                size_t o0 = (size_t)row * Nd + col;
                size_t o1 = (size_t)(row + 8) * Nd + col;
                if (res) {
                    v0 += res[o0]; v1 += res[o0 + 1];
                    v2 += res[o1]; v3 += res[o1 + 1];
                }
                C[o0] = v0; C[o0 + 1] = v1;
                C[o1] = v2; C[o1 + 1] = v3;
            }
        }
    }
}

// ---------------- silu(f1)*f2 -> f1 ----------------
__global__ void silumul_kernel(float* __restrict__ f1, const float* __restrict__ f2, int n) {
    int i = blockIdx.x * blockDim.x + threadIdx.x;
    if (i < n) {
        float a = f1[i];
        float s = a / (1.0f + __expf(-a));
        f1[i] = s * f2[i];
    }
}

// ---------------- host driver ----------------
extern "C" void kernel_launch(void* const* d_in, const int* in_sizes, int n_in,
                              void* d_out, int out_size) {
    const int*   tokens = (const int*)  d_in[0];
    const float* emb    = (const float*)d_in[1];
    const float* wq = (const float*)d_in[2];
    const float* bq = (const float*)d_in[3];
    const float* wk = (const float*)d_in[4];
    const float* bk = (const float*)d_in[5];
    const float* wv = (const float*)d_in[6];
    const float* bv = (const float*)d_in[7];
    const float* wo = (const float*)d_in[8];
    const float* bo = (const float*)d_in[9];
    const float* w1 = (const float*)d_in[10];
    const float* b1 = (const float*)d_in[11];
    const float* w2 = (const float*)d_in[12];
    const float* b2 = (const float*)d_in[13];
    const float* w3 = (const float*)d_in[14];
    const float* b3 = (const float*)d_in[15];
    const float* g1 = (const float*)d_in[16];
    const float* g2 = (const float*)d_in[17];
    const float* gpost = (const float*)d_in[18];
    const float* fcos  = (const float*)d_in[19];
    const float* fsin  = (const float*)d_in[20];
    float* out = (float*)d_out;

    float *x, *h, *q, *k, *v, *o, *f1, *f2;
    cudaGetSymbolAddress((void**)&x,  g_x);
    cudaGetSymbolAddress((void**)&h,  g_h);
    cudaGetSymbolAddress((void**)&q,  g_q);
    cudaGetSymbolAddress((void**)&k,  g_k);
    cudaGetSymbolAddress((void**)&v,  g_v);
    cudaGetSymbolAddress((void**)&o,  g_o);
    cudaGetSymbolAddress((void**)&f1, g_f1);
    cudaGetSymbolAddress((void**)&f2, g_f2);

    embed_kernel<<<MM, 256>>>(tokens, emb, x);

    const int KVN = KVH * DK;   // 512
    const int GY  = MM / BM;    // 32
    for (int l = 0; l < NL; l++) {
        rmsnorm_kernel<<<MM, 256>>>(x, g1 + (size_t)l * DD, h);

        gemm_tc_kernel<false><<<dim3(DD / BN, GY), 256>>>(
            h, wq + (size_t)l * DD * DD, bq + (size_t)l * DD, nullptr, q, DD, DD);
        gemm_tc_kernel<false><<<dim3(KVN / BN, GY), 256>>>(
            h, wk + (size_t)l * DD * KVN, bk + (size_t)l * KVN, nullptr, k, KVN, DD);
        gemm_tc_kernel<false><<<dim3(KVN / BN, GY), 256>>>(
            h, wv + (size_t)l * DD * KVN, bv + (size_t)l * KVN, nullptr, v, KVN, DD);

        int tq = MM * HH * 32,  tk = MM * KVH * 32;
        rope_kernel<<<(tq + 255) / 256, 256>>>(q, fcos, fsin, HH, tq);
        rope_kernel<<<(tk + 255) / 256, 256>>>(k, fcos, fsin, KVH, tk);

        attn_kernel<<<dim3(SS / ABM, HH, BB), dim3(32, 16)>>>(q, k, v, o);

        gemm_tc_kernel<false><<<dim3(DD / BN, GY), 256>>>(
            o, wo + (size_t)l * DD * DD, bo + (size_t)l * DD, x, x, DD, DD);

        rmsnorm_kernel<<<MM, 256>>>(x, g2 + (size_t)l * DD, h);

        int gnx = (FD + BN - 1) / BN;   // 22
        gemm_tc_kernel<false><<<dim3(gnx, GY), 256>>>(
            h, w1 + (size_t)l * DD * FD, b1 + (size_t)l * FD, nullptr, f1, FD, DD);
        gemm_tc_kernel<false><<<dim3(gnx, GY), 256>>>(
            h, w2 + (size_t)l * DD * FD, b2 + (size_t)l * FD, nullptr, f2, FD, DD);

        int nsm = MM * FD;
        silumul_kernel<<<(nsm + 255) / 256, 256>>>(f1, f2, nsm);

        gemm_tc_kernel<false><<<dim3(DD / BN, GY), 256>>>(
            f1, w3 + (size_t)l * FD * DD, b3 + (size_t)l * DD, x, x, DD, FD);
    }

    rmsnorm_kernel<<<MM, 256>>>(x, gpost, h);
    gemm_tc_kernel<true><<<dim3(VV / BN, GY), 256>>>(h, emb, nullptr, nullptr, out, VV, DD);
}